// round 1
// baseline (speedup 1.0000x reference)
#include <cuda_runtime.h>
#include <math.h>

#define B_SZ   2
#define S_LEN  2048
#define HID_   2048
#define NH     32
#define NKV    8
#define D_HEAD 64
#define M_FEAT 256
#define NC     16
#define CHUNK  128

// ---------------- scratch (device globals; no allocations allowed) ----------------
__device__ float g_q   [B_SZ * S_LEN * NH  * D_HEAD];   // (b*S+s, h*64+d)
__device__ float g_k   [B_SZ * S_LEN * NKV * D_HEAD];
__device__ float g_v   [B_SZ * S_LEN * NKV * D_HEAD];
__device__ float g_phiq[(size_t)B_SZ * NH  * S_LEN * M_FEAT];  // ((b*NH+h)*S+s, m)  xp then phi
__device__ float g_phik[(size_t)B_SZ * NKV * S_LEN * M_FEAT];
__device__ float g_sqq [B_SZ * NH  * S_LEN];
__device__ float g_sqk [B_SZ * NKV * S_LEN];
__device__ float g_stab[B_SZ * NKV];
__device__ float g_kv  [B_SZ * NKV * NC * M_FEAT * D_HEAD];    // per-chunk kv, then exclusive prefix
__device__ float g_kz  [B_SZ * NKV * NC * M_FEAT];
__device__ float g_attn[B_SZ * S_LEN * NH * D_HEAD];           // (b*S+s, h*64+d)

// ---------------- generic SGEMM: C(M,N) = A(M,K) @ W(N,K)^T, fp32 ----------------
// grid: (N/128, M/128), 256 threads, BK=16, 8x8 microtile
__global__ __launch_bounds__(256) void sgemm_nt(const float* __restrict__ A,
                                                const float* __restrict__ W,
                                                float* __restrict__ C,
                                                int N, int K)
{
    __shared__ float As[16][128];
    __shared__ float Bs[16][128];
    const int tid = threadIdx.x;
    const int tx = tid & 15, ty = tid >> 4;
    const float* Ab = A + (size_t)(blockIdx.y * 128) * K;
    const float* Wb = W + (size_t)(blockIdx.x * 128) * K;

    float acc[8][8];
#pragma unroll
    for (int i = 0; i < 8; i++)
#pragma unroll
        for (int j = 0; j < 8; j++) acc[i][j] = 0.f;

    for (int k0 = 0; k0 < K; k0 += 16) {
#pragma unroll
        for (int r = 0; r < 2; r++) {
            int l = tid + r * 256;
            int m = l >> 2, kq = (l & 3) << 2;
            float4 av = *(const float4*)(Ab + (size_t)m * K + k0 + kq);
            As[kq + 0][m] = av.x; As[kq + 1][m] = av.y;
            As[kq + 2][m] = av.z; As[kq + 3][m] = av.w;
            float4 bv = *(const float4*)(Wb + (size_t)m * K + k0 + kq);
            Bs[kq + 0][m] = bv.x; Bs[kq + 1][m] = bv.y;
            Bs[kq + 2][m] = bv.z; Bs[kq + 3][m] = bv.w;
        }
        __syncthreads();
#pragma unroll
        for (int kk = 0; kk < 16; kk++) {
            float a[8], b[8];
            *(float4*)&a[0] = *(const float4*)&As[kk][ty * 8];
            *(float4*)&a[4] = *(const float4*)&As[kk][ty * 8 + 4];
            *(float4*)&b[0] = *(const float4*)&Bs[kk][tx * 8];
            *(float4*)&b[4] = *(const float4*)&Bs[kk][tx * 8 + 4];
#pragma unroll
            for (int i = 0; i < 8; i++)
#pragma unroll
                for (int j = 0; j < 8; j++) acc[i][j] += a[i] * b[j];
        }
        __syncthreads();
    }
    const int col = blockIdx.x * 128 + tx * 8;
#pragma unroll
    for (int i = 0; i < 8; i++) {
        size_t row = (size_t)blockIdx.y * 128 + ty * 8 + i;
        float4* cp = (float4*)(C + row * N + col);
        cp[0] = make_float4(acc[i][0], acc[i][1], acc[i][2], acc[i][3]);
        cp[1] = make_float4(acc[i][4], acc[i][5], acc[i][6], acc[i][7]);
    }
}

// ---------------- RoPE, in place. grid = B*S rows, block = nheads*32 ----------------
__global__ void rope_kernel(float* __restrict__ x, const float* __restrict__ cosp,
                            const float* __restrict__ sinp, int nheads)
{
    const int row = blockIdx.x;            // b*S + s
    const int h = threadIdx.x >> 5, p = threadIdx.x & 31;
    const float c1 = cosp[row * 64 + p],      s1 = sinp[row * 64 + p];
    const float c2 = cosp[row * 64 + 32 + p], s2 = sinp[row * 64 + 32 + p];
    float* xr = x + ((size_t)row * nheads + h) * 64;
    const float x1 = xr[p], x2 = xr[p + 32];
    xr[p]      = x1 * c1 - x2 * s1;
    xr[p + 32] = x2 * c2 + x1 * s2;
}

__device__ void atomicMaxFloat(float* addr, float val)
{
    int* ia = (int*)addr;
    int old = *ia;
    while (__int_as_float(old) < val) {
        int assumed = old;
        old = atomicCAS(ia, assumed, __float_as_int(val));
        if (old == assumed) break;
    }
}

__global__ void init_stab_kernel(float* stab)
{
    if (threadIdx.x < B_SZ * NKV) stab[threadIdx.x] = -3.4e38f;
}

// ---------------- favor xp: xp = (x*dn) @ proj^T, also sq and (for k) head max ----
// grid: (S/32, nheads, B), 256 threads
__global__ __launch_bounds__(256) void favor_xp(const float* __restrict__ x,
                                                const float* __restrict__ proj,
                                                float* __restrict__ xp,
                                                float* __restrict__ sq,
                                                float* __restrict__ stab,
                                                int nheads)
{
    __shared__ float As[32 * 68];     // xn tile, padded rows
    __shared__ float Bs[16][256];     // proj^T tile
    __shared__ float red[256];
    const float DN = 0.35355339059327373f;   // 64^{-1/4}
    const int s0 = blockIdx.x * 32, h = blockIdx.y, b = blockIdx.z;
    const int tid = threadIdx.x;

#pragma unroll
    for (int r = 0; r < 2; r++) {
        int l = tid + r * 256;
        int tok = l >> 4, q4 = (l & 15) << 2;
        float4 vv = *(const float4*)(x + ((size_t)(b * S_LEN + s0 + tok) * nheads + h) * 64 + q4);
        As[tok * 68 + q4 + 0] = vv.x * DN;
        As[tok * 68 + q4 + 1] = vv.y * DN;
        As[tok * 68 + q4 + 2] = vv.z * DN;
        As[tok * 68 + q4 + 3] = vv.w * DN;
    }
    __syncthreads();
    if (tid < 32) {
        float ssum = 0.f;
#pragma unroll
        for (int d = 0; d < 64; d++) { float vv = As[tid * 68 + d]; ssum += vv * vv; }
        sq[((size_t)(b * nheads + h)) * S_LEN + s0 + tid] = 0.5f * ssum;
    }

    const int tg = tid >> 5, mg = tid & 31;    // 8 token-groups x 32 m-groups
    float acc[4][8];
#pragma unroll
    for (int i = 0; i < 4; i++)
#pragma unroll
        for (int j = 0; j < 8; j++) acc[i][j] = 0.f;

    for (int k0 = 0; k0 < 64; k0 += 16) {
#pragma unroll
        for (int j = 0; j < 4; j++) {
            float4 p = *(const float4*)(proj + tid * 64 + k0 + j * 4);
            Bs[j * 4 + 0][tid] = p.x; Bs[j * 4 + 1][tid] = p.y;
            Bs[j * 4 + 2][tid] = p.z; Bs[j * 4 + 3][tid] = p.w;
        }
        __syncthreads();
#pragma unroll
        for (int kk = 0; kk < 16; kk++) {
            float a[4];
#pragma unroll
            for (int i = 0; i < 4; i++) a[i] = As[(tg * 4 + i) * 68 + k0 + kk];
            float bb[8];
            *(float4*)&bb[0] = *(const float4*)&Bs[kk][mg * 8];
            *(float4*)&bb[4] = *(const float4*)&Bs[kk][mg * 8 + 4];
#pragma unroll
            for (int i = 0; i < 4; i++)
#pragma unroll
                for (int j = 0; j < 8; j++) acc[i][j] += a[i] * bb[j];
        }
        __syncthreads();
    }

    float mx = -3.4e38f;
    const size_t rowbase = (size_t)(b * nheads + h) * S_LEN + s0;
#pragma unroll
    for (int i = 0; i < 4; i++) {
        *(float4*)(xp + (rowbase + tg * 4 + i) * M_FEAT + mg * 8) =
            make_float4(acc[i][0], acc[i][1], acc[i][2], acc[i][3]);
        *(float4*)(xp + (rowbase + tg * 4 + i) * M_FEAT + mg * 8 + 4) =
            make_float4(acc[i][4], acc[i][5], acc[i][6], acc[i][7]);
        if (stab) {
#pragma unroll
            for (int j = 0; j < 8; j++) mx = fmaxf(mx, acc[i][j]);
        }
    }
    if (stab) {
        red[tid] = mx;
        __syncthreads();
        for (int st = 128; st > 0; st >>= 1) {
            if (tid < st) red[tid] = fmaxf(red[tid], red[tid + st]);
            __syncthreads();
        }
        if (tid == 0) atomicMaxFloat(&stab[b * nheads + h], red[0]);
    }
}

// ---------------- finalize phi in place: phi = (exp(xp - sq - stab) + eps)/16 ------
__global__ void favor_fin(float* __restrict__ xp, const float* __restrict__ sq,
                          const float* __restrict__ stab, int is_query, int nrows)
{
    const int warp = (blockIdx.x * blockDim.x + threadIdx.x) >> 5;
    const int lane = threadIdx.x & 31;
    if (warp >= nrows) return;
    float* row = xp + (size_t)warp * M_FEAT;
    float vals[8];
#pragma unroll
    for (int k = 0; k < 8; k++) vals[k] = row[lane + k * 32];
    float mx;
    if (is_query) {
        mx = vals[0];
#pragma unroll
        for (int k = 1; k < 8; k++) mx = fmaxf(mx, vals[k]);
#pragma unroll
        for (int o = 16; o > 0; o >>= 1) mx = fmaxf(mx, __shfl_xor_sync(0xffffffffu, mx, o));
    } else {
        mx = stab[warp / S_LEN];
    }
    const float sqv = sq[warp];
#pragma unroll
    for (int k = 0; k < 8; k++)
        row[lane + k * 32] = (expf(vals[k] - sqv - mx) + 1e-6f) * 0.0625f;
}

// ---------------- per-chunk kv (M x D) and kz (M). grid (NC, NKV, B) ---------------
__global__ __launch_bounds__(256) void kv_chunk(const float* __restrict__ phik,
                                                const float* __restrict__ v,
                                                float* __restrict__ kv,
                                                float* __restrict__ kz)
{
    __shared__ float ps[16][256];
    __shared__ float vs[16][64];
    const int c = blockIdx.x, h = blockIdx.y, b = blockIdx.z;
    const int tid = threadIdx.x;                    // m = tid
    float acc[64];
#pragma unroll
    for (int d = 0; d < 64; d++) acc[d] = 0.f;
    float accz = 0.f;
    const size_t prow = (size_t)(b * NKV + h) * S_LEN + c * CHUNK;
    const size_t vrow = (size_t)b * S_LEN + c * CHUNK;

    for (int i0 = 0; i0 < CHUNK; i0 += 16) {
#pragma unroll
        for (int ii = 0; ii < 16; ii++)
            ps[ii][tid] = phik[(prow + i0 + ii) * M_FEAT + tid];
#pragma unroll
        for (int j = 0; j < 4; j++) {
            int l = tid + j * 256;
            int ii = l >> 6, d = l & 63;
            vs[ii][d] = v[(vrow + i0 + ii) * (NKV * D_HEAD) + h * D_HEAD + d];
        }
        __syncthreads();
#pragma unroll
        for (int ii = 0; ii < 16; ii++) {
            float a = ps[ii][tid];
            accz += a;
#pragma unroll
            for (int d4 = 0; d4 < 64; d4 += 4) {
                float4 vv = *(const float4*)&vs[ii][d4];
                acc[d4 + 0] += a * vv.x; acc[d4 + 1] += a * vv.y;
                acc[d4 + 2] += a * vv.z; acc[d4 + 3] += a * vv.w;
            }
        }
        __syncthreads();
    }
    const size_t ob = (((size_t)(b * NKV + h) * NC + c) * M_FEAT + tid) * D_HEAD;
#pragma unroll
    for (int d4 = 0; d4 < 64; d4 += 4)
        *(float4*)(kv + ob + d4) = make_float4(acc[d4], acc[d4 + 1], acc[d4 + 2], acc[d4 + 3]);
    kz[((size_t)(b * NKV + h) * NC + c) * M_FEAT + tid] = accz;
}

// ---------------- exclusive prefix over chunk axis, in place ----------------------
__global__ void cumsum_k(float* __restrict__ kv, float* __restrict__ kz)
{
    const int tid = blockIdx.x * blockDim.x + threadIdx.x;
    const int KVSZ = M_FEAT * D_HEAD;            // 16384
    if (tid < B_SZ * NKV * KVSZ) {
        int bh = tid / KVSZ, md = tid % KVSZ;
        float run = 0.f;
        for (int c = 0; c < NC; c++) {
            size_t idx = ((size_t)bh * NC + c) * KVSZ + md;
            float t = kv[idx]; kv[idx] = run; run += t;
        }
    } else {
        int t2 = tid - B_SZ * NKV * KVSZ;
        if (t2 < B_SZ * NKV * M_FEAT) {
            int bh = t2 / M_FEAT, m = t2 % M_FEAT;
            float run = 0.f;
            for (int c = 0; c < NC; c++) {
                size_t idx = ((size_t)bh * NC + c) * M_FEAT + m;
                float tz = kz[idx]; kz[idx] = run; run += tz;
            }
        }
    }
}

// ---------------- chunked causal linear attention. grid (NC, NH, B) ---------------
__global__ __launch_bounds__(256) void attn_chunk(
    const float* __restrict__ phiq, const float* __restrict__ phik,
    const float* __restrict__ v, const float* __restrict__ kvpre,
    const float* __restrict__ kzpre, float* __restrict__ outp)
{
    extern __shared__ float sm[];
    float* Ss  = sm;                    // 128*129 masked scores
    float* Ast = sm + 128 * 129;        // 16*128  (qc^T tile)
    float* Bst = Ast + 16 * 128;        // 16*128  (kc^T tile)
    float* Vs  = Bst + 16 * 128;        // 16*64   (kvpre / v tile)
    float* KZs = Vs + 16 * 64;          // 16
    float* Zs  = KZs + 16;              // 128 denominators
    float* Z2  = Zs + 128;              // 256 intra_z partials

    const int c = blockIdx.x, h = blockIdx.y, b = blockIdx.z;
    const int kvh = h >> 2;
    const int tid = threadIdx.x;
    const int tx = tid & 15, ty = tid >> 4;

    const size_t qbase  = (size_t)(b * NH + h) * S_LEN + c * CHUNK;
    const size_t kbase  = (size_t)(b * NKV + kvh) * S_LEN + c * CHUNK;
    const size_t vbase  = (size_t)b * S_LEN + c * CHUNK;
    const size_t kvbase = ((size_t)(b * NKV + kvh) * NC + c) * (size_t)M_FEAT * D_HEAD;
    const size_t kzbase = ((size_t)(b * NKV + kvh) * NC + c) * M_FEAT;

    const int cr = tid >> 1, k8 = (tid & 1) * 8;

    // ---- Phase B: scores = mask(qc @ kc^T) -> Ss ----
    {
        float acc[8][8];
#pragma unroll
        for (int i = 0; i < 8; i++)
#pragma unroll
            for (int j = 0; j < 8; j++) acc[i][j] = 0.f;

        for (int m0 = 0; m0 < M_FEAT; m0 += 16) {
#pragma unroll
            for (int j = 0; j < 8; j += 4) {
                float4 qv = *(const float4*)(phiq + (qbase + cr) * M_FEAT + m0 + k8 + j);
                Ast[(k8 + j + 0) * 128 + cr] = qv.x;
                Ast[(k8 + j + 1) * 128 + cr] = qv.y;
                Ast[(k8 + j + 2) * 128 + cr] = qv.z;
                Ast[(k8 + j + 3) * 128 + cr] = qv.w;
                float4 kk4 = *(const float4*)(phik + (kbase + cr) * M_FEAT + m0 + k8 + j);
                Bst[(k8 + j + 0) * 128 + cr] = kk4.x;
                Bst[(k8 + j + 1) * 128 + cr] = kk4.y;
                Bst[(k8 + j + 2) * 128 + cr] = kk4.z;
                Bst[(k8 + j + 3) * 128 + cr] = kk4.w;
            }
            __syncthreads();
#pragma unroll
            for (int kk = 0; kk < 16; kk++) {
                float a[8], bb[8];
                *(float4*)&a[0]  = *(const float4*)&Ast[kk * 128 + ty * 8];
                *(float4*)&a[4]  = *(const float4*)&Ast[kk * 128 + ty * 8 + 4];
                *(float4*)&bb[0] = *(const float4*)&Bst[kk * 128 + tx * 8];
                *(float4*)&bb[4] = *(const float4*)&Bst[kk * 128 + tx * 8 + 4];
#pragma unroll
                for (int i = 0; i < 8; i++)
#pragma unroll
                    for (int j = 0; j < 8; j++) acc[i][j] += a[i] * bb[j];
            }
            __syncthreads();
        }
#pragma unroll
        for (int i = 0; i < 8; i++) {
            int r = ty * 8 + i;
#pragma unroll
            for (int j = 0; j < 8; j++) {
                int t = tx * 8 + j;
                Ss[r * 129 + t] = (t <= r) ? acc[i][j] : 0.f;
            }
        }
    }
    __syncthreads();

    // intra_z partial row sums (2 threads / row)
    {
        int r = tid >> 1, hf = tid & 1;
        float zz = 0.f;
#pragma unroll
        for (int t = 0; t < 64; t++) zz += Ss[r * 129 + hf * 64 + t];
        Z2[tid] = zz;
    }

    // ---- Phase A: inter = qc @ kv_pre, inter_z = qc @ kz_pre ----
    float acc2[8][4];
#pragma unroll
    for (int i = 0; i < 8; i++)
#pragma unroll
        for (int j = 0; j < 4; j++) acc2[i][j] = 0.f;
    float zreg = 0.f;

    for (int m0 = 0; m0 < M_FEAT; m0 += 16) {
#pragma unroll
        for (int j = 0; j < 8; j += 4) {
            float4 qv = *(const float4*)(phiq + (qbase + cr) * M_FEAT + m0 + k8 + j);
            Ast[(k8 + j + 0) * 128 + cr] = qv.x;
            Ast[(k8 + j + 1) * 128 + cr] = qv.y;
            Ast[(k8 + j + 2) * 128 + cr] = qv.z;
            Ast[(k8 + j + 3) * 128 + cr] = qv.w;
        }
        {
            float4 kvv = *(const float4*)(kvpre + kvbase + (size_t)(m0 + (tid >> 4)) * 64 + (tid & 15) * 4);
            *(float4*)&Vs[(tid >> 4) * 64 + (tid & 15) * 4] = kvv;
        }
        if (tid < 16) KZs[tid] = kzpre[kzbase + m0 + tid];
        __syncthreads();
#pragma unroll
        for (int kk = 0; kk < 16; kk++) {
            float a[8];
            *(float4*)&a[0] = *(const float4*)&Ast[kk * 128 + ty * 8];
            *(float4*)&a[4] = *(const float4*)&Ast[kk * 128 + ty * 8 + 4];
            float bb[4];
            *(float4*)&bb[0] = *(const float4*)&Vs[kk * 64 + tx * 4];
#pragma unroll
            for (int i = 0; i < 8; i++)
#pragma unroll
                for (int j = 0; j < 4; j++) acc2[i][j] += a[i] * bb[j];
        }
        if (tid < 128) {
#pragma unroll
            for (int kk = 0; kk < 16; kk++)
                zreg += Ast[kk * 128 + tid] * KZs[kk];
        }
        __syncthreads();
    }
    if (tid < 128) Zs[tid] = zreg;
    __syncthreads();
    if (tid < 128) Zs[tid] += Z2[2 * tid] + Z2[2 * tid + 1];
    __syncthreads();

    // ---- Phase C: intra = Ss @ vc, accumulated into acc2 ----
    for (int t0 = 0; t0 < CHUNK; t0 += 16) {
        float4 vv = *(const float4*)(v + (vbase + t0 + (tid >> 4)) * (NKV * D_HEAD) + kvh * D_HEAD + (tid & 15) * 4);
        *(float4*)&Vs[(tid >> 4) * 64 + (tid & 15) * 4] = vv;
        __syncthreads();
#pragma unroll
        for (int kk = 0; kk < 16; kk++) {
            float a[8];
#pragma unroll
            for (int i = 0; i < 8; i++) a[i] = Ss[(ty * 8 + i) * 129 + t0 + kk];
            float bb[4];
            *(float4*)&bb[0] = *(const float4*)&Vs[kk * 64 + tx * 4];
#pragma unroll
            for (int i = 0; i < 8; i++)
#pragma unroll
                for (int j = 0; j < 4; j++) acc2[i][j] += a[i] * bb[j];
        }
        __syncthreads();
    }

    // ---- write: (inter+intra) / (z + eps) into (b, s, h*64+d) ----
#pragma unroll
    for (int i = 0; i < 8; i++) {
        int r = ty * 8 + i;
        float dnm = 1.f / (Zs[r] + 1e-6f);
        float4 o = make_float4(acc2[i][0] * dnm, acc2[i][1] * dnm,
                               acc2[i][2] * dnm, acc2[i][3] * dnm);
        *(float4*)(outp + ((size_t)b * S_LEN + c * CHUNK + r) * (NH * D_HEAD) + h * D_HEAD + tx * 4) = o;
    }
}

// ----------------------------------- launch ---------------------------------------
extern "C" void kernel_launch(void* const* d_in, const int* in_sizes, int n_in,
                              void* d_out, int out_size)
{
    const float* hs   = (const float*)d_in[0];
    const float* cosp = (const float*)d_in[1];
    const float* sinp = (const float*)d_in[2];
    const float* Wq   = (const float*)d_in[3];
    const float* Wk   = (const float*)d_in[4];
    const float* Wv   = (const float*)d_in[5];
    const float* Wo   = (const float*)d_in[6];
    const float* proj = (const float*)d_in[7];
    float* out = (float*)d_out;

    float *qp, *kp, *vp, *phiqp, *phikp, *sqqp, *sqkp, *stabp, *kvp, *kzp, *attnp;
    cudaGetSymbolAddress((void**)&qp,    g_q);
    cudaGetSymbolAddress((void**)&kp,    g_k);
    cudaGetSymbolAddress((void**)&vp,    g_v);
    cudaGetSymbolAddress((void**)&phiqp, g_phiq);
    cudaGetSymbolAddress((void**)&phikp, g_phik);
    cudaGetSymbolAddress((void**)&sqqp,  g_sqq);
    cudaGetSymbolAddress((void**)&sqkp,  g_sqk);
    cudaGetSymbolAddress((void**)&stabp, g_stab);
    cudaGetSymbolAddress((void**)&kvp,   g_kv);
    cudaGetSymbolAddress((void**)&kzp,   g_kz);
    cudaGetSymbolAddress((void**)&attnp, g_attn);

    const int smem_attn = (128 * 129 + 2 * 16 * 128 + 16 * 64 + 16 + 128 + 256) * 4;
    cudaFuncSetAttribute(attn_chunk, cudaFuncAttributeMaxDynamicSharedMemorySize, smem_attn);

    // QKV projections
    sgemm_nt<<<dim3(16, 32), 256>>>(hs, Wq, qp, 2048, 2048);
    sgemm_nt<<<dim3(4, 32), 256>>>(hs, Wk, kp, 512, 2048);
    sgemm_nt<<<dim3(4, 32), 256>>>(hs, Wv, vp, 512, 2048);

    // RoPE
    rope_kernel<<<B_SZ * S_LEN, NH * 32>>>(qp, cosp, sinp, NH);
    rope_kernel<<<B_SZ * S_LEN, NKV * 32>>>(kp, cosp, sinp, NKV);

    // favor features
    init_stab_kernel<<<1, 32>>>(stabp);
    favor_xp<<<dim3(S_LEN / 32, NH, B_SZ), 256>>>(qp, proj, phiqp, sqqp, nullptr, NH);
    favor_xp<<<dim3(S_LEN / 32, NKV, B_SZ), 256>>>(kp, proj, phikp, sqkp, stabp, NKV);
    favor_fin<<<(B_SZ * NH * S_LEN) / 8, 256>>>(phiqp, sqqp, nullptr, 1, B_SZ * NH * S_LEN);
    favor_fin<<<(B_SZ * NKV * S_LEN) / 8, 256>>>(phikp, sqkp, stabp, 0, B_SZ * NKV * S_LEN);

    // chunked linear attention state
    kv_chunk<<<dim3(NC, NKV, B_SZ), 256>>>(phikp, vp, kvp, kzp);
    cumsum_k<<<(B_SZ * NKV * (M_FEAT * D_HEAD + M_FEAT) + 255) / 256, 256>>>(kvp, kzp);
    attn_chunk<<<dim3(NC, NH, B_SZ), 256, smem_attn>>>(phiqp, phikp, vp, kvp, kzp, attnp);

    // output projection
    sgemm_nt<<<dim3(16, 32), 256>>>(attnp, Wo, out, 2048, 2048);
}

// round 2
// speedup vs baseline: 1.6751x; 1.6751x over previous
#include <cuda_runtime.h>
#include <math.h>

#define B_SZ   2
#define S_LEN  2048
#define HID_   2048
#define NH     32
#define NKV    8
#define D_HEAD 64
#define M_FEAT 256
#define NC     16
#define CHUNK  128

// ---------------- scratch (device globals; no allocations allowed) ----------------
__device__ float g_q   [B_SZ * S_LEN * NH  * D_HEAD];   // (b*S+s, h*64+d)
__device__ float g_k   [B_SZ * S_LEN * NKV * D_HEAD];
__device__ float g_v   [B_SZ * S_LEN * NKV * D_HEAD];
__device__ float g_phiq[(size_t)B_SZ * NH  * S_LEN * M_FEAT];  // ((b*NH+h)*S+s, m)  xp then phi
__device__ float g_phik[(size_t)B_SZ * NKV * S_LEN * M_FEAT];
__device__ float g_sqq [B_SZ * NH  * S_LEN];
__device__ float g_sqk [B_SZ * NKV * S_LEN];
__device__ float g_stab[B_SZ * NKV];
__device__ float g_kv  [B_SZ * NKV * NC * M_FEAT * D_HEAD];    // per-chunk kv, then exclusive prefix
__device__ float g_kz  [B_SZ * NKV * NC * M_FEAT];
__device__ float g_attn[B_SZ * S_LEN * NH * D_HEAD];           // (b*S+s, h*64+d)

// =================== TF32 tensor-core GEMM: C(M,N) = A(M,K) @ W(N,K)^T =============
// grid (N/128, M/128), 256 threads. BK=32, double-buffered smem, 8 warps 2(m)x4(n).
// Each warp: 64(m) x 32(n) via 4x4 m16n8k8 tiles.

__device__ __forceinline__ unsigned f2tf32(float f)
{
    unsigned r;
    asm("cvt.rna.tf32.f32 %0, %1;" : "=r"(r) : "f"(f));
    return r;
}

__device__ __forceinline__ void mma_16n8k8(float c[4], const unsigned a[4], const unsigned b[2])
{
    asm volatile("mma.sync.aligned.m16n8k8.row.col.f32.tf32.tf32.f32 "
                 "{%0,%1,%2,%3}, {%4,%5,%6,%7}, {%8,%9}, {%0,%1,%2,%3};"
                 : "+f"(c[0]), "+f"(c[1]), "+f"(c[2]), "+f"(c[3])
                 : "r"(a[0]), "r"(a[1]), "r"(a[2]), "r"(a[3]), "r"(b[0]), "r"(b[1]));
}

#define TPITCH 136              // 32-row pitch, bank-conflict-free fragment loads
#define TBUF   (32 * TPITCH)    // floats per (A or B) buffer

__global__ __launch_bounds__(256) void gemm_tf32_nt(const float* __restrict__ A,
                                                    const float* __restrict__ W,
                                                    float* __restrict__ C,
                                                    int N, int K)
{
    extern __shared__ float sm[];
    float* Abuf[2] = { sm,              sm + 2 * TBUF };
    float* Bbuf[2] = { sm + TBUF,       sm + 3 * TBUF };

    const int tid  = threadIdx.x;
    const int warp = tid >> 5, lane = tid & 31;
    const int gid  = lane >> 2, tig = lane & 3;
    const int wm   = (warp & 1) * 64;        // warp m-offset
    const int wn   = (warp >> 1) * 32;       // warp n-offset

    const int lm = tid >> 1;                 // staging row (0..127)
    const int lk = (tid & 1) * 16;           // staging k-base

    const float* Ab = A + (size_t)(blockIdx.y * 128 + lm) * K + lk;
    const float* Wb = W + (size_t)(blockIdx.x * 128 + lm) * K + lk;

    float acc[4][4][4];
#pragma unroll
    for (int i = 0; i < 4; i++)
#pragma unroll
        for (int j = 0; j < 4; j++)
#pragma unroll
            for (int r = 0; r < 4; r++) acc[i][j][r] = 0.f;

    float4 ar[4], br[4];

    // ---- prologue: load tile 0 ----
#pragma unroll
    for (int j = 0; j < 4; j++) {
        ar[j] = *(const float4*)(Ab + j * 4);
        br[j] = *(const float4*)(Wb + j * 4);
    }
#pragma unroll
    for (int j = 0; j < 4; j++) {
        int kb = lk + j * 4;
        Abuf[0][(kb + 0) * TPITCH + lm] = __uint_as_float(f2tf32(ar[j].x));
        Abuf[0][(kb + 1) * TPITCH + lm] = __uint_as_float(f2tf32(ar[j].y));
        Abuf[0][(kb + 2) * TPITCH + lm] = __uint_as_float(f2tf32(ar[j].z));
        Abuf[0][(kb + 3) * TPITCH + lm] = __uint_as_float(f2tf32(ar[j].w));
        Bbuf[0][(kb + 0) * TPITCH + lm] = __uint_as_float(f2tf32(br[j].x));
        Bbuf[0][(kb + 1) * TPITCH + lm] = __uint_as_float(f2tf32(br[j].y));
        Bbuf[0][(kb + 2) * TPITCH + lm] = __uint_as_float(f2tf32(br[j].z));
        Bbuf[0][(kb + 3) * TPITCH + lm] = __uint_as_float(f2tf32(br[j].w));
    }
    __syncthreads();

    const int NT = K / 32;
    for (int kt = 0; kt < NT; kt++) {
        const int buf = kt & 1;
        // ---- prefetch next tile into regs ----
        if (kt + 1 < NT) {
            const float* An = Ab + (size_t)(kt + 1) * 32;
            const float* Wn = Wb + (size_t)(kt + 1) * 32;
#pragma unroll
            for (int j = 0; j < 4; j++) {
                ar[j] = *(const float4*)(An + j * 4);
                br[j] = *(const float4*)(Wn + j * 4);
            }
        }
        // ---- compute on current buffer ----
        const float* As = Abuf[buf];
        const float* Bs = Bbuf[buf];
#pragma unroll
        for (int ks = 0; ks < 4; ks++) {
            const int kb = ks * 8;
            unsigned af[4][4], bf[4][2];
#pragma unroll
            for (int tm = 0; tm < 4; tm++) {
                const int rm = wm + tm * 16;
                af[tm][0] = __float_as_uint(As[(kb + tig)     * TPITCH + rm + gid]);
                af[tm][1] = __float_as_uint(As[(kb + tig)     * TPITCH + rm + gid + 8]);
                af[tm][2] = __float_as_uint(As[(kb + tig + 4) * TPITCH + rm + gid]);
                af[tm][3] = __float_as_uint(As[(kb + tig + 4) * TPITCH + rm + gid + 8]);
            }
#pragma unroll
            for (int tn = 0; tn < 4; tn++) {
                const int cn = wn + tn * 8;
                bf[tn][0] = __float_as_uint(Bs[(kb + tig)     * TPITCH + cn + gid]);
                bf[tn][1] = __float_as_uint(Bs[(kb + tig + 4) * TPITCH + cn + gid]);
            }
#pragma unroll
            for (int tm = 0; tm < 4; tm++)
#pragma unroll
                for (int tn = 0; tn < 4; tn++)
                    mma_16n8k8(acc[tm][tn], af[tm], bf[tn]);
        }
        // ---- store next tile into other buffer ----
        if (kt + 1 < NT) {
            float* An = Abuf[buf ^ 1];
            float* Bn = Bbuf[buf ^ 1];
#pragma unroll
            for (int j = 0; j < 4; j++) {
                int kb = lk + j * 4;
                An[(kb + 0) * TPITCH + lm] = __uint_as_float(f2tf32(ar[j].x));
                An[(kb + 1) * TPITCH + lm] = __uint_as_float(f2tf32(ar[j].y));
                An[(kb + 2) * TPITCH + lm] = __uint_as_float(f2tf32(ar[j].z));
                An[(kb + 3) * TPITCH + lm] = __uint_as_float(f2tf32(ar[j].w));
                Bn[(kb + 0) * TPITCH + lm] = __uint_as_float(f2tf32(br[j].x));
                Bn[(kb + 1) * TPITCH + lm] = __uint_as_float(f2tf32(br[j].y));
                Bn[(kb + 2) * TPITCH + lm] = __uint_as_float(f2tf32(br[j].z));
                Bn[(kb + 3) * TPITCH + lm] = __uint_as_float(f2tf32(br[j].w));
            }
        }
        __syncthreads();
    }

    // ---- epilogue ----
#pragma unroll
    for (int tm = 0; tm < 4; tm++) {
        const size_t r0 = (size_t)blockIdx.y * 128 + wm + tm * 16 + gid;
#pragma unroll
        for (int tn = 0; tn < 4; tn++) {
            const int cn = blockIdx.x * 128 + wn + tn * 8 + tig * 2;
            *(float2*)(C + r0 * N + cn)       = make_float2(acc[tm][tn][0], acc[tm][tn][1]);
            *(float2*)(C + (r0 + 8) * N + cn) = make_float2(acc[tm][tn][2], acc[tm][tn][3]);
        }
    }
}

// ---------------- RoPE, in place. grid = B*S rows, block = nheads*32 ----------------
__global__ void rope_kernel(float* __restrict__ x, const float* __restrict__ cosp,
                            const float* __restrict__ sinp, int nheads)
{
    const int row = blockIdx.x;            // b*S + s
    const int h = threadIdx.x >> 5, p = threadIdx.x & 31;
    const float c1 = cosp[row * 64 + p],      s1 = sinp[row * 64 + p];
    const float c2 = cosp[row * 64 + 32 + p], s2 = sinp[row * 64 + 32 + p];
    float* xr = x + ((size_t)row * nheads + h) * 64;
    const float x1 = xr[p], x2 = xr[p + 32];
    xr[p]      = x1 * c1 - x2 * s1;
    xr[p + 32] = x2 * c2 + x1 * s2;
}

__device__ void atomicMaxFloat(float* addr, float val)
{
    int* ia = (int*)addr;
    int old = *ia;
    while (__int_as_float(old) < val) {
        int assumed = old;
        old = atomicCAS(ia, assumed, __float_as_int(val));
        if (old == assumed) break;
    }
}

__global__ void init_stab_kernel(float* stab)
{
    if (threadIdx.x < B_SZ * NKV) stab[threadIdx.x] = -3.4e38f;
}

// ---------------- favor xp: xp = (x*dn) @ proj^T, also sq and (for k) head max ----
// grid: (S/32, nheads, B), 256 threads
__global__ __launch_bounds__(256) void favor_xp(const float* __restrict__ x,
                                                const float* __restrict__ proj,
                                                float* __restrict__ xp,
                                                float* __restrict__ sq,
                                                float* __restrict__ stab,
                                                int nheads)
{
    __shared__ float As[32 * 68];     // xn tile, padded rows
    __shared__ float Bs[16][256];     // proj^T tile
    __shared__ float red[256];
    const float DN = 0.35355339059327373f;   // 64^{-1/4}
    const int s0 = blockIdx.x * 32, h = blockIdx.y, b = blockIdx.z;
    const int tid = threadIdx.x;

#pragma unroll
    for (int r = 0; r < 2; r++) {
        int l = tid + r * 256;
        int tok = l >> 4, q4 = (l & 15) << 2;
        float4 vv = *(const float4*)(x + ((size_t)(b * S_LEN + s0 + tok) * nheads + h) * 64 + q4);
        As[tok * 68 + q4 + 0] = vv.x * DN;
        As[tok * 68 + q4 + 1] = vv.y * DN;
        As[tok * 68 + q4 + 2] = vv.z * DN;
        As[tok * 68 + q4 + 3] = vv.w * DN;
    }
    __syncthreads();
    if (tid < 32) {
        float ssum = 0.f;
#pragma unroll
        for (int d = 0; d < 64; d++) { float vv = As[tid * 68 + d]; ssum += vv * vv; }
        sq[((size_t)(b * nheads + h)) * S_LEN + s0 + tid] = 0.5f * ssum;
    }

    const int tg = tid >> 5, mg = tid & 31;    // 8 token-groups x 32 m-groups
    float acc[4][8];
#pragma unroll
    for (int i = 0; i < 4; i++)
#pragma unroll
        for (int j = 0; j < 8; j++) acc[i][j] = 0.f;

    for (int k0 = 0; k0 < 64; k0 += 16) {
#pragma unroll
        for (int j = 0; j < 4; j++) {
            float4 p = *(const float4*)(proj + tid * 64 + k0 + j * 4);
            Bs[j * 4 + 0][tid] = p.x; Bs[j * 4 + 1][tid] = p.y;
            Bs[j * 4 + 2][tid] = p.z; Bs[j * 4 + 3][tid] = p.w;
        }
        __syncthreads();
#pragma unroll
        for (int kk = 0; kk < 16; kk++) {
            float a[4];
#pragma unroll
            for (int i = 0; i < 4; i++) a[i] = As[(tg * 4 + i) * 68 + k0 + kk];
            float bb[8];
            *(float4*)&bb[0] = *(const float4*)&Bs[kk][mg * 8];
            *(float4*)&bb[4] = *(const float4*)&Bs[kk][mg * 8 + 4];
#pragma unroll
            for (int i = 0; i < 4; i++)
#pragma unroll
                for (int j = 0; j < 8; j++) acc[i][j] += a[i] * bb[j];
        }
        __syncthreads();
    }

    float mx = -3.4e38f;
    const size_t rowbase = (size_t)(b * nheads + h) * S_LEN + s0;
#pragma unroll
    for (int i = 0; i < 4; i++) {
        *(float4*)(xp + (rowbase + tg * 4 + i) * M_FEAT + mg * 8) =
            make_float4(acc[i][0], acc[i][1], acc[i][2], acc[i][3]);
        *(float4*)(xp + (rowbase + tg * 4 + i) * M_FEAT + mg * 8 + 4) =
            make_float4(acc[i][4], acc[i][5], acc[i][6], acc[i][7]);
        if (stab) {
#pragma unroll
            for (int j = 0; j < 8; j++) mx = fmaxf(mx, acc[i][j]);
        }
    }
    if (stab) {
        red[tid] = mx;
        __syncthreads();
        for (int st = 128; st > 0; st >>= 1) {
            if (tid < st) red[tid] = fmaxf(red[tid], red[tid + st]);
            __syncthreads();
        }
        if (tid == 0) atomicMaxFloat(&stab[b * nheads + h], red[0]);
    }
}

// ---------------- finalize phi in place: phi = (exp(xp - sq - stab) + eps)/16 ------
__global__ void favor_fin(float* __restrict__ xp, const float* __restrict__ sq,
                          const float* __restrict__ stab, int is_query, int nrows)
{
    const int warp = (blockIdx.x * blockDim.x + threadIdx.x) >> 5;
    const int lane = threadIdx.x & 31;
    if (warp >= nrows) return;
    float* row = xp + (size_t)warp * M_FEAT;
    float vals[8];
#pragma unroll
    for (int k = 0; k < 8; k++) vals[k] = row[lane + k * 32];
    float mx;
    if (is_query) {
        mx = vals[0];
#pragma unroll
        for (int k = 1; k < 8; k++) mx = fmaxf(mx, vals[k]);
#pragma unroll
        for (int o = 16; o > 0; o >>= 1) mx = fmaxf(mx, __shfl_xor_sync(0xffffffffu, mx, o));
    } else {
        mx = stab[warp / S_LEN];
    }
    const float sqv = sq[warp];
#pragma unroll
    for (int k = 0; k < 8; k++)
        row[lane + k * 32] = (expf(vals[k] - sqv - mx) + 1e-6f) * 0.0625f;
}

// ---------------- per-chunk kv (M x D) and kz (M). grid (NC, NKV, B) ---------------
__global__ __launch_bounds__(256) void kv_chunk(const float* __restrict__ phik,
                                                const float* __restrict__ v,
                                                float* __restrict__ kv,
                                                float* __restrict__ kz)
{
    __shared__ float ps[16][256];
    __shared__ float vs[16][64];
    const int c = blockIdx.x, h = blockIdx.y, b = blockIdx.z;
    const int tid = threadIdx.x;                    // m = tid
    float acc[64];
#pragma unroll
    for (int d = 0; d < 64; d++) acc[d] = 0.f;
    float accz = 0.f;
    const size_t prow = (size_t)(b * NKV + h) * S_LEN + c * CHUNK;
    const size_t vrow = (size_t)b * S_LEN + c * CHUNK;

    for (int i0 = 0; i0 < CHUNK; i0 += 16) {
#pragma unroll
        for (int ii = 0; ii < 16; ii++)
            ps[ii][tid] = phik[(prow + i0 + ii) * M_FEAT + tid];
#pragma unroll
        for (int j = 0; j < 4; j++) {
            int l = tid + j * 256;
            int ii = l >> 6, d = l & 63;
            vs[ii][d] = v[(vrow + i0 + ii) * (NKV * D_HEAD) + h * D_HEAD + d];
        }
        __syncthreads();
#pragma unroll
        for (int ii = 0; ii < 16; ii++) {
            float a = ps[ii][tid];
            accz += a;
#pragma unroll
            for (int d4 = 0; d4 < 64; d4 += 4) {
                float4 vv = *(const float4*)&vs[ii][d4];
                acc[d4 + 0] += a * vv.x; acc[d4 + 1] += a * vv.y;
                acc[d4 + 2] += a * vv.z; acc[d4 + 3] += a * vv.w;
            }
        }
        __syncthreads();
    }
    const size_t ob = (((size_t)(b * NKV + h) * NC + c) * M_FEAT + tid) * D_HEAD;
#pragma unroll
    for (int d4 = 0; d4 < 64; d4 += 4)
        *(float4*)(kv + ob + d4) = make_float4(acc[d4], acc[d4 + 1], acc[d4 + 2], acc[d4 + 3]);
    kz[((size_t)(b * NKV + h) * NC + c) * M_FEAT + tid] = accz;
}

// ---------------- exclusive prefix over chunk axis, in place ----------------------
__global__ void cumsum_k(float* __restrict__ kv, float* __restrict__ kz)
{
    const int tid = blockIdx.x * blockDim.x + threadIdx.x;
    const int KVSZ = M_FEAT * D_HEAD;            // 16384
    if (tid < B_SZ * NKV * KVSZ) {
        int bh = tid / KVSZ, md = tid % KVSZ;
        float run = 0.f;
        for (int c = 0; c < NC; c++) {
            size_t idx = ((size_t)bh * NC + c) * KVSZ + md;
            float t = kv[idx]; kv[idx] = run; run += t;
        }
    } else {
        int t2 = tid - B_SZ * NKV * KVSZ;
        if (t2 < B_SZ * NKV * M_FEAT) {
            int bh = t2 / M_FEAT, m = t2 % M_FEAT;
            float run = 0.f;
            for (int c = 0; c < NC; c++) {
                size_t idx = ((size_t)bh * NC + c) * M_FEAT + m;
                float tz = kz[idx]; kz[idx] = run; run += tz;
            }
        }
    }
}

// ---------------- chunked causal linear attention. grid (NC, NH, B) ---------------
__global__ __launch_bounds__(256) void attn_chunk(
    const float* __restrict__ phiq, const float* __restrict__ phik,
    const float* __restrict__ v, const float* __restrict__ kvpre,
    const float* __restrict__ kzpre, float* __restrict__ outp)
{
    extern __shared__ float sm[];
    float* Ss  = sm;                    // 128*129 masked scores
    float* Ast = sm + 128 * 129;        // 16*128  (qc^T tile)
    float* Bst = Ast + 16 * 128;        // 16*128  (kc^T tile)
    float* Vs  = Bst + 16 * 128;        // 16*64   (kvpre / v tile)
    float* KZs = Vs + 16 * 64;          // 16
    float* Zs  = KZs + 16;              // 128 denominators
    float* Z2  = Zs + 128;              // 256 intra_z partials

    const int c = blockIdx.x, h = blockIdx.y, b = blockIdx.z;
    const int kvh = h >> 2;
    const int tid = threadIdx.x;
    const int tx = tid & 15, ty = tid >> 4;

    const size_t qbase  = (size_t)(b * NH + h) * S_LEN + c * CHUNK;
    const size_t kbase  = (size_t)(b * NKV + kvh) * S_LEN + c * CHUNK;
    const size_t vbase  = (size_t)b * S_LEN + c * CHUNK;
    const size_t kvbase = ((size_t)(b * NKV + kvh) * NC + c) * (size_t)M_FEAT * D_HEAD;
    const size_t kzbase = ((size_t)(b * NKV + kvh) * NC + c) * M_FEAT;

    const int cr = tid >> 1, k8 = (tid & 1) * 8;

    // ---- Phase B: scores = mask(qc @ kc^T) -> Ss ----
    {
        float acc[8][8];
#pragma unroll
        for (int i = 0; i < 8; i++)
#pragma unroll
            for (int j = 0; j < 8; j++) acc[i][j] = 0.f;

        for (int m0 = 0; m0 < M_FEAT; m0 += 16) {
#pragma unroll
            for (int j = 0; j < 8; j += 4) {
                float4 qv = *(const float4*)(phiq + (qbase + cr) * M_FEAT + m0 + k8 + j);
                Ast[(k8 + j + 0) * 128 + cr] = qv.x;
                Ast[(k8 + j + 1) * 128 + cr] = qv.y;
                Ast[(k8 + j + 2) * 128 + cr] = qv.z;
                Ast[(k8 + j + 3) * 128 + cr] = qv.w;
                float4 kk4 = *(const float4*)(phik + (kbase + cr) * M_FEAT + m0 + k8 + j);
                Bst[(k8 + j + 0) * 128 + cr] = kk4.x;
                Bst[(k8 + j + 1) * 128 + cr] = kk4.y;
                Bst[(k8 + j + 2) * 128 + cr] = kk4.z;
                Bst[(k8 + j + 3) * 128 + cr] = kk4.w;
            }
            __syncthreads();
#pragma unroll
            for (int kk = 0; kk < 16; kk++) {
                float a[8], bb[8];
                *(float4*)&a[0]  = *(const float4*)&Ast[kk * 128 + ty * 8];
                *(float4*)&a[4]  = *(const float4*)&Ast[kk * 128 + ty * 8 + 4];
                *(float4*)&bb[0] = *(const float4*)&Bst[kk * 128 + tx * 8];
                *(float4*)&bb[4] = *(const float4*)&Bst[kk * 128 + tx * 8 + 4];
#pragma unroll
                for (int i = 0; i < 8; i++)
#pragma unroll
                    for (int j = 0; j < 8; j++) acc[i][j] += a[i] * bb[j];
            }
            __syncthreads();
        }
#pragma unroll
        for (int i = 0; i < 8; i++) {
            int r = ty * 8 + i;
#pragma unroll
            for (int j = 0; j < 8; j++) {
                int t = tx * 8 + j;
                Ss[r * 129 + t] = (t <= r) ? acc[i][j] : 0.f;
            }
        }
    }
    __syncthreads();

    // intra_z partial row sums (2 threads / row)
    {
        int r = tid >> 1, hf = tid & 1;
        float zz = 0.f;
#pragma unroll
        for (int t = 0; t < 64; t++) zz += Ss[r * 129 + hf * 64 + t];
        Z2[tid] = zz;
    }

    // ---- Phase A: inter = qc @ kv_pre, inter_z = qc @ kz_pre ----
    float acc2[8][4];
#pragma unroll
    for (int i = 0; i < 8; i++)
#pragma unroll
        for (int j = 0; j < 4; j++) acc2[i][j] = 0.f;
    float zreg = 0.f;

    for (int m0 = 0; m0 < M_FEAT; m0 += 16) {
#pragma unroll
        for (int j = 0; j < 8; j += 4) {
            float4 qv = *(const float4*)(phiq + (qbase + cr) * M_FEAT + m0 + k8 + j);
            Ast[(k8 + j + 0) * 128 + cr] = qv.x;
            Ast[(k8 + j + 1) * 128 + cr] = qv.y;
            Ast[(k8 + j + 2) * 128 + cr] = qv.z;
            Ast[(k8 + j + 3) * 128 + cr] = qv.w;
        }
        {
            float4 kvv = *(const float4*)(kvpre + kvbase + (size_t)(m0 + (tid >> 4)) * 64 + (tid & 15) * 4);
            *(float4*)&Vs[(tid >> 4) * 64 + (tid & 15) * 4] = kvv;
        }
        if (tid < 16) KZs[tid] = kzpre[kzbase + m0 + tid];
        __syncthreads();
#pragma unroll
        for (int kk = 0; kk < 16; kk++) {
            float a[8];
            *(float4*)&a[0] = *(const float4*)&Ast[kk * 128 + ty * 8];
            *(float4*)&a[4] = *(const float4*)&Ast[kk * 128 + ty * 8 + 4];
            float bb[4];
            *(float4*)&bb[0] = *(const float4*)&Vs[kk * 64 + tx * 4];
#pragma unroll
            for (int i = 0; i < 8; i++)
#pragma unroll
                for (int j = 0; j < 4; j++) acc2[i][j] += a[i] * bb[j];
        }
        if (tid < 128) {
#pragma unroll
            for (int kk = 0; kk < 16; kk++)
                zreg += Ast[kk * 128 + tid] * KZs[kk];
        }
        __syncthreads();
    }
    if (tid < 128) Zs[tid] = zreg;
    __syncthreads();
    if (tid < 128) Zs[tid] += Z2[2 * tid] + Z2[2 * tid + 1];
    __syncthreads();

    // ---- Phase C: intra = Ss @ vc, accumulated into acc2 ----
    for (int t0 = 0; t0 < CHUNK; t0 += 16) {
        float4 vv = *(const float4*)(v + (vbase + t0 + (tid >> 4)) * (NKV * D_HEAD) + kvh * D_HEAD + (tid & 15) * 4);
        *(float4*)&Vs[(tid >> 4) * 64 + (tid & 15) * 4] = vv;
        __syncthreads();
#pragma unroll
        for (int kk = 0; kk < 16; kk++) {
            float a[8];
#pragma unroll
            for (int i = 0; i < 8; i++) a[i] = Ss[(ty * 8 + i) * 129 + t0 + kk];
            float bb[4];
            *(float4*)&bb[0] = *(const float4*)&Vs[kk * 64 + tx * 4];
#pragma unroll
            for (int i = 0; i < 8; i++)
#pragma unroll
                for (int j = 0; j < 4; j++) acc2[i][j] += a[i] * bb[j];
        }
        __syncthreads();
    }

    // ---- write: (inter+intra) / (z + eps) into (b, s, h*64+d) ----
#pragma unroll
    for (int i = 0; i < 8; i++) {
        int r = ty * 8 + i;
        float dnm = 1.f / (Zs[r] + 1e-6f);
        float4 o = make_float4(acc2[i][0] * dnm, acc2[i][1] * dnm,
                               acc2[i][2] * dnm, acc2[i][3] * dnm);
        *(float4*)(outp + ((size_t)b * S_LEN + c * CHUNK + r) * (NH * D_HEAD) + h * D_HEAD + tx * 4) = o;
    }
}

// ----------------------------------- launch ---------------------------------------
extern "C" void kernel_launch(void* const* d_in, const int* in_sizes, int n_in,
                              void* d_out, int out_size)
{
    const float* hs   = (const float*)d_in[0];
    const float* cosp = (const float*)d_in[1];
    const float* sinp = (const float*)d_in[2];
    const float* Wq   = (const float*)d_in[3];
    const float* Wk   = (const float*)d_in[4];
    const float* Wv   = (const float*)d_in[5];
    const float* Wo   = (const float*)d_in[6];
    const float* proj = (const float*)d_in[7];
    float* out = (float*)d_out;

    float *qp, *kp, *vp, *phiqp, *phikp, *sqqp, *sqkp, *stabp, *kvp, *kzp, *attnp;
    cudaGetSymbolAddress((void**)&qp,    g_q);
    cudaGetSymbolAddress((void**)&kp,    g_k);
    cudaGetSymbolAddress((void**)&vp,    g_v);
    cudaGetSymbolAddress((void**)&phiqp, g_phiq);
    cudaGetSymbolAddress((void**)&phikp, g_phik);
    cudaGetSymbolAddress((void**)&sqqp,  g_sqq);
    cudaGetSymbolAddress((void**)&sqkp,  g_sqk);
    cudaGetSymbolAddress((void**)&stabp, g_stab);
    cudaGetSymbolAddress((void**)&kvp,   g_kv);
    cudaGetSymbolAddress((void**)&kzp,   g_kz);
    cudaGetSymbolAddress((void**)&attnp, g_attn);

    const int smem_attn = (128 * 129 + 2 * 16 * 128 + 16 * 64 + 16 + 128 + 256) * 4;
    cudaFuncSetAttribute(attn_chunk, cudaFuncAttributeMaxDynamicSharedMemorySize, smem_attn);

    const int smem_gemm = 4 * TBUF * 4;   // 69632 B
    cudaFuncSetAttribute(gemm_tf32_nt, cudaFuncAttributeMaxDynamicSharedMemorySize, smem_gemm);

    // QKV projections (TF32 tensor cores)
    gemm_tf32_nt<<<dim3(16, 32), 256, smem_gemm>>>(hs, Wq, qp, 2048, 2048);
    gemm_tf32_nt<<<dim3(4, 32), 256, smem_gemm>>>(hs, Wk, kp, 512, 2048);
    gemm_tf32_nt<<<dim3(4, 32), 256, smem_gemm>>>(hs, Wv, vp, 512, 2048);

    // RoPE
    rope_kernel<<<B_SZ * S_LEN, NH * 32>>>(qp, cosp, sinp, NH);
    rope_kernel<<<B_SZ * S_LEN, NKV * 32>>>(kp, cosp, sinp, NKV);

    // favor features
    init_stab_kernel<<<1, 32>>>(stabp);
    favor_xp<<<dim3(S_LEN / 32, NH, B_SZ), 256>>>(qp, proj, phiqp, sqqp, nullptr, NH);
    favor_xp<<<dim3(S_LEN / 32, NKV, B_SZ), 256>>>(kp, proj, phikp, sqkp, stabp, NKV);
    favor_fin<<<(B_SZ * NH * S_LEN) / 8, 256>>>(phiqp, sqqp, nullptr, 1, B_SZ * NH * S_LEN);
    favor_fin<<<(B_SZ * NKV * S_LEN) / 8, 256>>>(phikp, sqkp, stabp, 0, B_SZ * NKV * S_LEN);

    // chunked linear attention state
    kv_chunk<<<dim3(NC, NKV, B_SZ), 256>>>(phikp, vp, kvp, kzp);
    cumsum_k<<<(B_SZ * NKV * (M_FEAT * D_HEAD + M_FEAT) + 255) / 256, 256>>>(kvp, kzp);
    attn_chunk<<<dim3(NC, NH, B_SZ), 256, smem_attn>>>(phiqp, phikp, vp, kvp, kzp, attnp);

    // output projection (TF32 tensor cores)
    gemm_tf32_nt<<<dim3(16, 32), 256, smem_gemm>>>(attnp, Wo, out, 2048, 2048);
}